// round 15
// baseline (speedup 1.0000x reference)
#include <cuda_runtime.h>
#include <cuda_fp16.h>
#include <math.h>
#include <stdint.h>

#define NN 100000
#define CC 128
#define EE 600000
#define HH 64
#define NUNITS (EE / 16)        // 37500 16-edge warp units, exact
#define MAIN_GRID 608           // 152 SMs * 4 persistent
#define MAIN_THREADS 256
#define NWARPS_TOTAL (MAIN_GRID * (MAIN_THREADS / 32))   // 4864

#define APW 68                  // A pitch in 32-bit words (fp16x2 units): 64 + 4 pad

// SMEM float offsets
#define OFF_A   0               // 128*68 = 8704 words
#define OFF_BP  8704            // packed B frags: 8*4*32 uint4 = 4096 words
#define OFF_B1  12800           // 64
#define OFF_W2  12864           // 64
#define SMEM_FLOATS 12928       // 51712 bytes -> 4 blocks/SM (207KB)

// Node tables in fp16: v1 = z_out + z_self, v2 = z_in + z_self (25.6 MB each).
__device__ uint4 g_v1h[(size_t)NN * CC / 8];
__device__ uint4 g_v2h[(size_t)NN * CC / 8];
__device__ unsigned int g_unit_ctr;   // reset by prep_kernel each launch

__device__ __forceinline__ uint32_t f2h2(float lo, float hi) {
    uint32_t r;
    asm("cvt.rn.f16x2.f32 %0, %1, %2;" : "=r"(r) : "f"(hi), "f"(lo));
    return r;
}

__global__ void prep_kernel(const float* __restrict__ z_in,
                            const float* __restrict__ z_out,
                            const float* __restrict__ z_self) {
    const int i = blockIdx.x * blockDim.x + threadIdx.x;   // 8 channels / thread
    if (i == 0) g_unit_ctr = NWARPS_TOTAL;                 // reset stealing ctr
    const float4* zi = (const float4*)z_in;
    const float4* zo = (const float4*)z_out;
    const float4* zs = (const float4*)z_self;
    const float4 s0 = zs[2 * i],     s1 = zs[2 * i + 1];
    const float4 a0 = zo[2 * i],     a1 = zo[2 * i + 1];
    const float4 b0 = zi[2 * i],     b1 = zi[2 * i + 1];
    uint4 o1, o2;
    o1.x = f2h2(a0.x + s0.x, a0.y + s0.y);
    o1.y = f2h2(a0.z + s0.z, a0.w + s0.w);
    o1.z = f2h2(a1.x + s1.x, a1.y + s1.y);
    o1.w = f2h2(a1.z + s1.z, a1.w + s1.w);
    o2.x = f2h2(b0.x + s0.x, b0.y + s0.y);
    o2.y = f2h2(b0.z + s0.z, b0.w + s0.w);
    o2.z = f2h2(b1.x + s1.x, b1.y + s1.y);
    o2.w = f2h2(b1.z + s1.z, b1.w + s1.w);
    g_v1h[i] = o1;
    g_v2h[i] = o2;
    // Allow the dependent (gemm) grid to begin launching now that all of this
    // thread's table stores are issued (completion ordered by griddepcontrol.wait).
    asm volatile("griddepcontrol.launch_dependents;" ::: "memory");
}

__device__ __forceinline__ void mma_f16(float* c,
                                        uint32_t a0, uint32_t a1, uint32_t a2, uint32_t a3,
                                        uint32_t b0, uint32_t b1) {
    asm volatile(
        "mma.sync.aligned.m16n8k16.row.col.f32.f16.f16.f32 "
        "{%0,%1,%2,%3}, {%4,%5,%6,%7}, {%8,%9}, {%0,%1,%2,%3};"
        : "+f"(c[0]), "+f"(c[1]), "+f"(c[2]), "+f"(c[3])
        : "r"(a0), "r"(a1), "r"(a2), "r"(a3), "r"(b0), "r"(b1));
}

// Fused gather + GEMM (fp16 mma.sync) + ELU + GEMV + sigmoid.
// PDL secondary: stages weights (inputs prep never writes) BEFORE
// griddepcontrol.wait, then consumes the fp16 node tables.
// Warp owns its 16 As rows; 16-edge units claimed via atomic stealing.
__global__ __launch_bounds__(MAIN_THREADS, 4)
void gemm_kernel(const int* __restrict__ eidx,
                 const float* __restrict__ W1,
                 const float* __restrict__ b1,
                 const float* __restrict__ W2,
                 const float* __restrict__ b2,
                 float* __restrict__ out)
{
    extern __shared__ float smem[];
    uint32_t* Au  = (uint32_t*)(smem + OFF_A);
    uint4*    Bp  = (uint4*)(smem + OFF_BP);
    float*    b1s = smem + OFF_B1;
    float*    w2s = smem + OFF_W2;

    const int tid  = threadIdx.x;
    const int lane = tid & 31;
    const int warp = tid >> 5;
    const int gid  = lane >> 2;   // 0..7
    const int tig  = lane & 3;    // 0..3
    const int wb   = warp * 16;   // A-row base for this warp (fixed)
    const int lw   = lane & 15;
    const int hi   = lane >> 4;   // edge parity within a pair

    // ---- Stage packed-B frags (fp16) + vectors (pre-wait: prep-independent) ----
    for (int i = tid; i < 8 * 4 * 32; i += MAIN_THREADS) {
        const int l   = i & 31;
        const int nt2 = (i >> 5) & 3;
        const int ks  = i >> 7;
        const int g   = l >> 2;
        const int t   = l & 3;
        const int k0  = ks * 16;
        const int n0  = nt2 * 16 + g;
        const int n1  = n0 + 8;
        uint4 v;
        v.x = f2h2(W1[(k0 + 2 * t) * HH + n0],     W1[(k0 + 2 * t + 1) * HH + n0]);
        v.y = f2h2(W1[(k0 + 2 * t + 8) * HH + n0], W1[(k0 + 2 * t + 9) * HH + n0]);
        v.z = f2h2(W1[(k0 + 2 * t) * HH + n1],     W1[(k0 + 2 * t + 1) * HH + n1]);
        v.w = f2h2(W1[(k0 + 2 * t + 8) * HH + n1], W1[(k0 + 2 * t + 9) * HH + n1]);
        Bp[i] = v;
    }
    if (tid < HH) { b1s[tid] = b1[tid]; w2s[tid] = W2[tid]; }
    const float b2v = b2[0];

    // ---- Wait for prep's node tables (and counter reset) to be visible ----
    asm volatile("griddepcontrol.wait;" ::: "memory");
    __syncthreads();

    const int* srcI = eidx;
    const int* dstI = eidx + EE;
    const char* t1b = (const char*)g_v1h;
    const char* t2b = (const char*)g_v2h;
    const unsigned laneOff = (unsigned)lw * 16u;

    int unit = blockIdx.x * (MAIN_THREADS / 32) + warp;   // initial assignment

    while (unit < NUNITS) {
        // Steal next unit early; latency hidden behind this unit's work.
        int nxt;
        if (lane == 0) nxt = (int)atomicAdd(&g_unit_ctr, 1u);
        nxt = __shfl_sync(0xffffffffu, nxt, 0);

        const int e0 = unit * 16;

        // ---- Gather 16 edges (2/iter via LDG.128) into As rows [wb, wb+16) ----
        {
            const unsigned myOff =
                (unsigned)((lane < 16) ? srcI[e0 + lw] : dstI[e0 + lw]) * 256u;
            #pragma unroll
            for (int b = 0; b < 4; b++) {
                uint4 va[2], vb[2];
                #pragma unroll
                for (int j = 0; j < 2; j++) {
                    const int i = 2 * b + j;          // edge pair: 2i, 2i+1
                    const unsigned so = __shfl_sync(0xffffffffu, myOff, 2 * i + hi);
                    const unsigned dofs = __shfl_sync(0xffffffffu, myOff, 16 + 2 * i + hi);
                    va[j] = *(const uint4*)(t1b + so + laneOff);
                    vb[j] = *(const uint4*)(t2b + dofs + laneOff);
                }
                #pragma unroll
                for (int j = 0; j < 2; j++) {
                    const int i = 2 * b + j;
                    uint4 p;
                    asm("mul.rn.f16x2 %0, %1, %2;" : "=r"(p.x) : "r"(va[j].x), "r"(vb[j].x));
                    asm("mul.rn.f16x2 %0, %1, %2;" : "=r"(p.y) : "r"(va[j].y), "r"(vb[j].y));
                    asm("mul.rn.f16x2 %0, %1, %2;" : "=r"(p.z) : "r"(va[j].z), "r"(vb[j].z));
                    asm("mul.rn.f16x2 %0, %1, %2;" : "=r"(p.w) : "r"(va[j].w), "r"(vb[j].w));
                    *(uint4*)(Au + (wb + 2 * i + hi) * APW + lw * 4) = p;   // STS.128
                }
            }
        }
        __syncwarp();   // STS visible to all lanes' LDS below

        // ---- GEMM: D[16x64] = A[16x128] x B[128x64], k16 steps ----
        float acc[8][4];
        #pragma unroll
        for (int nt = 0; nt < 8; nt++)
            #pragma unroll
            for (int c = 0; c < 4; c++) acc[nt][c] = 0.f;

        #pragma unroll
        for (int ks = 0; ks < 8; ks++) {
            const uint32_t* ar = Au + (wb + gid) * APW + 8 * ks + tig;
            const uint32_t a0 = ar[0];            // row gid,   k lo pair
            const uint32_t a2 = ar[4];            // row gid,   k hi pair
            const uint32_t a1 = ar[8 * APW];      // row gid+8, k lo pair
            const uint32_t a3 = ar[8 * APW + 4];  // row gid+8, k hi pair
            #pragma unroll
            for (int nt2 = 0; nt2 < 4; nt2++) {
                const uint4 bf = Bp[(ks * 4 + nt2) * 32 + lane];
                mma_f16(acc[2 * nt2],     a0, a1, a2, a3, bf.x, bf.y);
                mma_f16(acc[2 * nt2 + 1], a0, a1, a2, a3, bf.z, bf.w);
            }
        }
        __syncwarp();   // all lanes' A-LDS done before next unit's STS rewrite

        // ---- Epilogue: bias + ELU + dot(W2), 4-lane shfl reduce, sigmoid ----
        float p0 = 0.f, p1 = 0.f;
        #pragma unroll
        for (int nt = 0; nt < 8; nt++) {
            const int n = nt * 8 + 2 * tig;
            const float2 bb = *(const float2*)(b1s + n);   // LDS.64
            const float2 ww = *(const float2*)(w2s + n);   // LDS.64
            float x;
            x = acc[nt][0] + bb.x; p0 = fmaf(x > 0.f ? x : (__expf(x) - 1.f), ww.x, p0);
            x = acc[nt][1] + bb.y; p0 = fmaf(x > 0.f ? x : (__expf(x) - 1.f), ww.y, p0);
            x = acc[nt][2] + bb.x; p1 = fmaf(x > 0.f ? x : (__expf(x) - 1.f), ww.x, p1);
            x = acc[nt][3] + bb.y; p1 = fmaf(x > 0.f ? x : (__expf(x) - 1.f), ww.y, p1);
        }
        p0 += __shfl_xor_sync(0xffffffffu, p0, 1);
        p0 += __shfl_xor_sync(0xffffffffu, p0, 2);
        p1 += __shfl_xor_sync(0xffffffffu, p1, 1);
        p1 += __shfl_xor_sync(0xffffffffu, p1, 2);
        if (tig == 0) {
            out[e0 + gid]     = 1.0f / (1.0f + __expf(-(p0 + b2v)));
            out[e0 + gid + 8] = 1.0f / (1.0f + __expf(-(p1 + b2v)));
        }

        unit = nxt;
    }
}

extern "C" void kernel_launch(void* const* d_in, const int* in_sizes, int n_in,
                              void* d_out, int out_size) {
    const float* z_in   = (const float*)d_in[0];
    const float* z_out  = (const float*)d_in[1];
    const float* z_self = (const float*)d_in[2];
    const int*   eidx   = (const int*)d_in[3];
    const float* W1     = (const float*)d_in[4];
    const float* b1     = (const float*)d_in[5];
    const float* W2     = (const float*)d_in[6];
    const float* b2     = (const float*)d_in[7];
    float*       outp   = (float*)d_out;

    prep_kernel<<<NN * CC / 8 / 256, 256>>>(z_in, z_out, z_self);

    const int smem_bytes = SMEM_FLOATS * (int)sizeof(float);   // 51712
    cudaFuncSetAttribute(gemm_kernel,
                         cudaFuncAttributeMaxDynamicSharedMemorySize, smem_bytes);

    // PDL secondary launch: may begin while prep drains; device-side
    // griddepcontrol.wait gates table consumption.
    cudaLaunchConfig_t cfg = {};
    cfg.gridDim = dim3(MAIN_GRID, 1, 1);
    cfg.blockDim = dim3(MAIN_THREADS, 1, 1);
    cfg.dynamicSmemBytes = smem_bytes;
    cfg.stream = 0;
    cudaLaunchAttribute attrs[1];
    attrs[0].id = cudaLaunchAttributeProgrammaticStreamSerialization;
    attrs[0].val.programmaticStreamSerializationAllowed = 1;
    cfg.attrs = attrs;
    cfg.numAttrs = 1;
    cudaLaunchKernelEx(&cfg, gemm_kernel, eidx, W1, b1, W2, b2, outp);
}

// round 16
// speedup vs baseline: 1.0141x; 1.0141x over previous
#include <cuda_runtime.h>
#include <cuda_fp16.h>
#include <math.h>
#include <stdint.h>

#define NN 100000
#define CC 128
#define EE 600000
#define HH 64
#define NUNITS (EE / 16)        // 37500 16-edge warp units, exact
#define MAIN_GRID 608           // 152 SMs * 4 persistent
#define MAIN_THREADS 256
#define NWARPS_TOTAL (MAIN_GRID * (MAIN_THREADS / 32))   // 4864

#define APW 68                  // A pitch in 32-bit words (fp16x2 units): 64 + 4 pad

// SMEM float offsets
#define OFF_A   0               // 128*68 = 8704 words
#define OFF_BP  8704            // packed B frags: 8*4*32 uint4 = 4096 words
#define OFF_B1  12800           // 64
#define OFF_W2  12864           // 64
#define SMEM_FLOATS 12928       // 51712 bytes -> 4 blocks/SM (207KB)

// Node tables in fp16: v1 = z_out + z_self, v2 = z_in + z_self (25.6 MB each).
__device__ uint4 g_v1h[(size_t)NN * CC / 8];
__device__ uint4 g_v2h[(size_t)NN * CC / 8];
__device__ unsigned int g_unit_ctr;   // reset by prep_kernel each launch

__device__ __forceinline__ uint32_t f2h2(float lo, float hi) {
    uint32_t r;
    asm("cvt.rn.f16x2.f32 %0, %1, %2;" : "=r"(r) : "f"(hi), "f"(lo));
    return r;
}

__global__ void prep_kernel(const float* __restrict__ z_in,
                            const float* __restrict__ z_out,
                            const float* __restrict__ z_self) {
    const int i = blockIdx.x * blockDim.x + threadIdx.x;   // 8 channels / thread
    if (i == 0) g_unit_ctr = NWARPS_TOTAL;                 // reset stealing ctr
    const float4* zi = (const float4*)z_in;
    const float4* zo = (const float4*)z_out;
    const float4* zs = (const float4*)z_self;
    const float4 s0 = zs[2 * i],     s1 = zs[2 * i + 1];
    const float4 a0 = zo[2 * i],     a1 = zo[2 * i + 1];
    const float4 b0 = zi[2 * i],     b1 = zi[2 * i + 1];
    uint4 o1, o2;
    o1.x = f2h2(a0.x + s0.x, a0.y + s0.y);
    o1.y = f2h2(a0.z + s0.z, a0.w + s0.w);
    o1.z = f2h2(a1.x + s1.x, a1.y + s1.y);
    o1.w = f2h2(a1.z + s1.z, a1.w + s1.w);
    o2.x = f2h2(b0.x + s0.x, b0.y + s0.y);
    o2.y = f2h2(b0.z + s0.z, b0.w + s0.w);
    o2.z = f2h2(b1.x + s1.x, b1.y + s1.y);
    o2.w = f2h2(b1.z + s1.z, b1.w + s1.w);
    g_v1h[i] = o1;
    g_v2h[i] = o2;
    // Allow the dependent (gemm) grid to begin launching now that all of this
    // thread's table stores are issued (completion ordered by griddepcontrol.wait).
    asm volatile("griddepcontrol.launch_dependents;" ::: "memory");
}

__device__ __forceinline__ void mma_f16(float* c,
                                        uint32_t a0, uint32_t a1, uint32_t a2, uint32_t a3,
                                        uint32_t b0, uint32_t b1) {
    asm volatile(
        "mma.sync.aligned.m16n8k16.row.col.f32.f16.f16.f32 "
        "{%0,%1,%2,%3}, {%4,%5,%6,%7}, {%8,%9}, {%0,%1,%2,%3};"
        : "+f"(c[0]), "+f"(c[1]), "+f"(c[2]), "+f"(c[3])
        : "r"(a0), "r"(a1), "r"(a2), "r"(a3), "r"(b0), "r"(b1));
}

// Fused gather + GEMM (fp16 mma.sync) + ELU + GEMV + sigmoid.
// PDL secondary: stages weights (inputs prep never writes) BEFORE
// griddepcontrol.wait, then consumes the fp16 node tables.
// Warp owns its 16 As rows; 16-edge units claimed via atomic stealing.
// Gather: batched exchange-free LDG.64 (R14 form — fastest measured).
__global__ __launch_bounds__(MAIN_THREADS, 4)
void gemm_kernel(const int* __restrict__ eidx,
                 const float* __restrict__ W1,
                 const float* __restrict__ b1,
                 const float* __restrict__ W2,
                 const float* __restrict__ b2,
                 float* __restrict__ out)
{
    extern __shared__ float smem[];
    uint32_t* Au  = (uint32_t*)(smem + OFF_A);
    uint4*    Bp  = (uint4*)(smem + OFF_BP);
    float*    b1s = smem + OFF_B1;
    float*    w2s = smem + OFF_W2;

    const int tid  = threadIdx.x;
    const int lane = tid & 31;
    const int warp = tid >> 5;
    const int gid  = lane >> 2;   // 0..7
    const int tig  = lane & 3;    // 0..3
    const int wb   = warp * 16;   // A-row base for this warp (fixed)
    const int lw   = lane & 15;

    // ---- Stage packed-B frags (fp16) + vectors (pre-wait: prep-independent) ----
    for (int i = tid; i < 8 * 4 * 32; i += MAIN_THREADS) {
        const int l   = i & 31;
        const int nt2 = (i >> 5) & 3;
        const int ks  = i >> 7;
        const int g   = l >> 2;
        const int t   = l & 3;
        const int k0  = ks * 16;
        const int n0  = nt2 * 16 + g;
        const int n1  = n0 + 8;
        uint4 v;
        v.x = f2h2(W1[(k0 + 2 * t) * HH + n0],     W1[(k0 + 2 * t + 1) * HH + n0]);
        v.y = f2h2(W1[(k0 + 2 * t + 8) * HH + n0], W1[(k0 + 2 * t + 9) * HH + n0]);
        v.z = f2h2(W1[(k0 + 2 * t) * HH + n1],     W1[(k0 + 2 * t + 1) * HH + n1]);
        v.w = f2h2(W1[(k0 + 2 * t + 8) * HH + n1], W1[(k0 + 2 * t + 9) * HH + n1]);
        Bp[i] = v;
    }
    if (tid < HH) { b1s[tid] = b1[tid]; w2s[tid] = W2[tid]; }
    const float b2v = b2[0];

    // ---- Wait for prep's node tables (and counter reset) to be visible ----
    asm volatile("griddepcontrol.wait;" ::: "memory");
    __syncthreads();

    const int* srcI = eidx;
    const int* dstI = eidx + EE;
    const char* t1b = (const char*)g_v1h;
    const char* t2b = (const char*)g_v2h;
    const unsigned laneOff = (unsigned)lane * 8u;

    int unit = blockIdx.x * (MAIN_THREADS / 32) + warp;   // initial assignment

    while (unit < NUNITS) {
        // Steal next unit early; latency hidden behind this unit's work.
        int nxt;
        if (lane == 0) nxt = (int)atomicAdd(&g_unit_ctr, 1u);
        nxt = __shfl_sync(0xffffffffu, nxt, 0);

        const int e0 = unit * 16;

        // ---- Gather 16 edges into As rows [wb, wb+16), 4-edge LDG.64 batches ----
        {
            const unsigned myOff =
                (unsigned)((lane < 16) ? srcI[e0 + lw] : dstI[e0 + lw]) * 256u;
            #pragma unroll
            for (int b = 0; b < 4; b++) {
                uint2 va[4], vb[4];
                #pragma unroll
                for (int j = 0; j < 4; j++) {
                    const int i = b * 4 + j;
                    const unsigned so = __shfl_sync(0xffffffffu, myOff, i);
                    const unsigned dofs = __shfl_sync(0xffffffffu, myOff, 16 + i);
                    va[j] = *(const uint2*)(t1b + so + laneOff);
                    vb[j] = *(const uint2*)(t2b + dofs + laneOff);
                }
                #pragma unroll
                for (int j = 0; j < 4; j++) {
                    const int i = b * 4 + j;
                    uint2 p;
                    asm("mul.rn.f16x2 %0, %1, %2;" : "=r"(p.x) : "r"(va[j].x), "r"(vb[j].x));
                    asm("mul.rn.f16x2 %0, %1, %2;" : "=r"(p.y) : "r"(va[j].y), "r"(vb[j].y));
                    *(uint2*)(Au + (wb + i) * APW + lane * 2) = p;   // STS.64
                }
            }
        }
        __syncwarp();   // STS visible to all lanes' LDS below

        // ---- GEMM: D[16x64] = A[16x128] x B[128x64], k16 steps ----
        float acc[8][4];
        #pragma unroll
        for (int nt = 0; nt < 8; nt++)
            #pragma unroll
            for (int c = 0; c < 4; c++) acc[nt][c] = 0.f;

        #pragma unroll
        for (int ks = 0; ks < 8; ks++) {
            const uint32_t* ar = Au + (wb + gid) * APW + 8 * ks + tig;
            const uint32_t a0 = ar[0];            // row gid,   k lo pair
            const uint32_t a2 = ar[4];            // row gid,   k hi pair
            const uint32_t a1 = ar[8 * APW];      // row gid+8, k lo pair
            const uint32_t a3 = ar[8 * APW + 4];  // row gid+8, k hi pair
            #pragma unroll
            for (int nt2 = 0; nt2 < 4; nt2++) {
                const uint4 bf = Bp[(ks * 4 + nt2) * 32 + lane];
                mma_f16(acc[2 * nt2],     a0, a1, a2, a3, bf.x, bf.y);
                mma_f16(acc[2 * nt2 + 1], a0, a1, a2, a3, bf.z, bf.w);
            }
        }
        __syncwarp();   // all lanes' A-LDS done before next unit's STS rewrite

        // ---- Epilogue: bias + ELU + dot(W2), 4-lane shfl reduce, sigmoid ----
        float p0 = 0.f, p1 = 0.f;
        #pragma unroll
        for (int nt = 0; nt < 8; nt++) {
            const int n = nt * 8 + 2 * tig;
            const float2 bb = *(const float2*)(b1s + n);   // LDS.64
            const float2 ww = *(const float2*)(w2s + n);   // LDS.64
            float x;
            x = acc[nt][0] + bb.x; p0 = fmaf(x > 0.f ? x : (__expf(x) - 1.f), ww.x, p0);
            x = acc[nt][1] + bb.y; p0 = fmaf(x > 0.f ? x : (__expf(x) - 1.f), ww.y, p0);
            x = acc[nt][2] + bb.x; p1 = fmaf(x > 0.f ? x : (__expf(x) - 1.f), ww.x, p1);
            x = acc[nt][3] + bb.y; p1 = fmaf(x > 0.f ? x : (__expf(x) - 1.f), ww.y, p1);
        }
        p0 += __shfl_xor_sync(0xffffffffu, p0, 1);
        p0 += __shfl_xor_sync(0xffffffffu, p0, 2);
        p1 += __shfl_xor_sync(0xffffffffu, p1, 1);
        p1 += __shfl_xor_sync(0xffffffffu, p1, 2);
        if (tig == 0) {
            out[e0 + gid]     = 1.0f / (1.0f + __expf(-(p0 + b2v)));
            out[e0 + gid + 8] = 1.0f / (1.0f + __expf(-(p1 + b2v)));
        }

        unit = nxt;
    }
}

extern "C" void kernel_launch(void* const* d_in, const int* in_sizes, int n_in,
                              void* d_out, int out_size) {
    const float* z_in   = (const float*)d_in[0];
    const float* z_out  = (const float*)d_in[1];
    const float* z_self = (const float*)d_in[2];
    const int*   eidx   = (const int*)d_in[3];
    const float* W1     = (const float*)d_in[4];
    const float* b1     = (const float*)d_in[5];
    const float* W2     = (const float*)d_in[6];
    const float* b2     = (const float*)d_in[7];
    float*       outp   = (float*)d_out;

    prep_kernel<<<NN * CC / 8 / 256, 256>>>(z_in, z_out, z_self);

    const int smem_bytes = SMEM_FLOATS * (int)sizeof(float);   // 51712
    cudaFuncSetAttribute(gemm_kernel,
                         cudaFuncAttributeMaxDynamicSharedMemorySize, smem_bytes);

    // PDL secondary launch: may begin while prep drains; device-side
    // griddepcontrol.wait gates table consumption.
    cudaLaunchConfig_t cfg = {};
    cfg.gridDim = dim3(MAIN_GRID, 1, 1);
    cfg.blockDim = dim3(MAIN_THREADS, 1, 1);
    cfg.dynamicSmemBytes = smem_bytes;
    cfg.stream = 0;
    cudaLaunchAttribute attrs[1];
    attrs[0].id = cudaLaunchAttributeProgrammaticStreamSerialization;
    attrs[0].val.programmaticStreamSerializationAllowed = 1;
    cfg.attrs = attrs;
    cfg.numAttrs = 1;
    cudaLaunchKernelEx(&cfg, gemm_kernel, eidx, W1, b1, W2, b2, outp);
}

// round 17
// speedup vs baseline: 1.0163x; 1.0022x over previous
#include <cuda_runtime.h>
#include <cuda_fp16.h>
#include <math.h>
#include <stdint.h>

#define NN 100000
#define CC 128
#define EE 600000
#define HH 64
#define NUNITS (EE / 16)        // 37500 16-edge warp units, exact
#define MAIN_GRID 608           // 152 SMs * 4 persistent
#define MAIN_THREADS 256
#define NWARPS_TOTAL (MAIN_GRID * (MAIN_THREADS / 32))   // 4864

#define APW 68                  // A pitch in 32-bit words (fp16x2 units): 64 + 4 pad

// SMEM float offsets
#define OFF_A   0               // 128*68 = 8704 words
#define OFF_BP  8704            // packed B frags: 8*4*32 uint4 = 4096 words
#define OFF_B1  12800           // 64
#define OFF_W2  12864           // 64
#define SMEM_FLOATS 12928       // 51712 bytes -> 4 blocks/SM (207KB)

// Node tables in fp16: v1 = z_out + z_self, v2 = z_in + z_self (25.6 MB each).
__device__ uint4 g_v1h[(size_t)NN * CC / 8];
__device__ uint4 g_v2h[(size_t)NN * CC / 8];
__device__ unsigned int g_unit_ctr;   // reset by prep_kernel each launch

__device__ __forceinline__ uint32_t f2h2(float lo, float hi) {
    uint32_t r;
    asm("cvt.rn.f16x2.f32 %0, %1, %2;" : "=r"(r) : "f"(hi), "f"(lo));
    return r;
}

__global__ void prep_kernel(const float* __restrict__ z_in,
                            const float* __restrict__ z_out,
                            const float* __restrict__ z_self) {
    const int i = blockIdx.x * blockDim.x + threadIdx.x;   // 8 channels / thread
    if (i == 0) g_unit_ctr = NWARPS_TOTAL;                 // reset stealing ctr
    const float4* zi = (const float4*)z_in;
    const float4* zo = (const float4*)z_out;
    const float4* zs = (const float4*)z_self;
    const float4 s0 = zs[2 * i],     s1 = zs[2 * i + 1];
    const float4 a0 = zo[2 * i],     a1 = zo[2 * i + 1];
    const float4 b0 = zi[2 * i],     b1 = zi[2 * i + 1];
    uint4 o1, o2;
    o1.x = f2h2(a0.x + s0.x, a0.y + s0.y);
    o1.y = f2h2(a0.z + s0.z, a0.w + s0.w);
    o1.z = f2h2(a1.x + s1.x, a1.y + s1.y);
    o1.w = f2h2(a1.z + s1.z, a1.w + s1.w);
    o2.x = f2h2(b0.x + s0.x, b0.y + s0.y);
    o2.y = f2h2(b0.z + s0.z, b0.w + s0.w);
    o2.z = f2h2(b1.x + s1.x, b1.y + s1.y);
    o2.w = f2h2(b1.z + s1.z, b1.w + s1.w);
    g_v1h[i] = o1;
    g_v2h[i] = o2;
    // Allow the dependent (gemm) grid to begin launching now that all of this
    // thread's table stores are issued (completion ordered by griddepcontrol.wait).
    asm volatile("griddepcontrol.launch_dependents;" ::: "memory");
}

__device__ __forceinline__ void mma_f16(float* c,
                                        uint32_t a0, uint32_t a1, uint32_t a2, uint32_t a3,
                                        uint32_t b0, uint32_t b1) {
    asm volatile(
        "mma.sync.aligned.m16n8k16.row.col.f32.f16.f16.f32 "
        "{%0,%1,%2,%3}, {%4,%5,%6,%7}, {%8,%9}, {%0,%1,%2,%3};"
        : "+f"(c[0]), "+f"(c[1]), "+f"(c[2]), "+f"(c[3])
        : "r"(a0), "r"(a1), "r"(a2), "r"(a3), "r"(b0), "r"(b1));
}

// Fused gather + GEMM (fp16 mma.sync) + ELU + GEMV + sigmoid.
// PDL secondary; atomic work stealing with NEXT-unit edge-index prefetch:
// the eidx load for unit n+1 issues right after the steal, hiding its
// L2 latency under unit n's mma + epilogue.
__global__ __launch_bounds__(MAIN_THREADS, 4)
void gemm_kernel(const int* __restrict__ eidx,
                 const float* __restrict__ W1,
                 const float* __restrict__ b1,
                 const float* __restrict__ W2,
                 const float* __restrict__ b2,
                 float* __restrict__ out)
{
    extern __shared__ float smem[];
    uint32_t* Au  = (uint32_t*)(smem + OFF_A);
    uint4*    Bp  = (uint4*)(smem + OFF_BP);
    float*    b1s = smem + OFF_B1;
    float*    w2s = smem + OFF_W2;

    const int tid  = threadIdx.x;
    const int lane = tid & 31;
    const int warp = tid >> 5;
    const int gid  = lane >> 2;   // 0..7
    const int tig  = lane & 3;    // 0..3
    const int wb   = warp * 16;   // A-row base for this warp (fixed)
    const int lw   = lane & 15;

    // ---- Stage packed-B frags (fp16) + vectors (pre-wait: prep-independent) ----
    for (int i = tid; i < 8 * 4 * 32; i += MAIN_THREADS) {
        const int l   = i & 31;
        const int nt2 = (i >> 5) & 3;
        const int ks  = i >> 7;
        const int g   = l >> 2;
        const int t   = l & 3;
        const int k0  = ks * 16;
        const int n0  = nt2 * 16 + g;
        const int n1  = n0 + 8;
        uint4 v;
        v.x = f2h2(W1[(k0 + 2 * t) * HH + n0],     W1[(k0 + 2 * t + 1) * HH + n0]);
        v.y = f2h2(W1[(k0 + 2 * t + 8) * HH + n0], W1[(k0 + 2 * t + 9) * HH + n0]);
        v.z = f2h2(W1[(k0 + 2 * t) * HH + n1],     W1[(k0 + 2 * t + 1) * HH + n1]);
        v.w = f2h2(W1[(k0 + 2 * t + 8) * HH + n1], W1[(k0 + 2 * t + 9) * HH + n1]);
        Bp[i] = v;
    }
    if (tid < HH) { b1s[tid] = b1[tid]; w2s[tid] = W2[tid]; }
    const float b2v = b2[0];

    // ---- Wait for prep's node tables (and counter reset) to be visible ----
    asm volatile("griddepcontrol.wait;" ::: "memory");
    __syncthreads();

    const int* srcI = eidx;
    const int* dstI = eidx + EE;
    const char* t1b = (const char*)g_v1h;
    const char* t2b = (const char*)g_v2h;
    const unsigned laneOff = (unsigned)lane * 8u;

    int unit = blockIdx.x * (MAIN_THREADS / 32) + warp;   // initial assignment
    // Prefetch the initial unit's edge indices (byte offsets).
    unsigned myOff =
        (unsigned)((lane < 16) ? srcI[unit * 16 + lw] : dstI[unit * 16 + lw]) * 256u;

    while (unit < NUNITS) {
        // Steal next unit; immediately prefetch ITS edge indices (clamped if
        // out of range — value discarded). Latency hidden by this unit's work.
        int nxt;
        if (lane == 0) nxt = (int)atomicAdd(&g_unit_ctr, 1u);
        nxt = __shfl_sync(0xffffffffu, nxt, 0);
        const int eN = (nxt < NUNITS ? nxt : 0) * 16 + lw;
        const unsigned nxtOff =
            (unsigned)((lane < 16) ? srcI[eN] : dstI[eN]) * 256u;

        const int e0 = unit * 16;

        // ---- Gather 16 edges into As rows [wb, wb+16), 4-edge LDG.64 batches ----
        {
            #pragma unroll
            for (int b = 0; b < 4; b++) {
                uint2 va[4], vb[4];
                #pragma unroll
                for (int j = 0; j < 4; j++) {
                    const int i = b * 4 + j;
                    const unsigned so = __shfl_sync(0xffffffffu, myOff, i);
                    const unsigned dofs = __shfl_sync(0xffffffffu, myOff, 16 + i);
                    va[j] = *(const uint2*)(t1b + so + laneOff);
                    vb[j] = *(const uint2*)(t2b + dofs + laneOff);
                }
                #pragma unroll
                for (int j = 0; j < 4; j++) {
                    const int i = b * 4 + j;
                    uint2 p;
                    asm("mul.rn.f16x2 %0, %1, %2;" : "=r"(p.x) : "r"(va[j].x), "r"(vb[j].x));
                    asm("mul.rn.f16x2 %0, %1, %2;" : "=r"(p.y) : "r"(va[j].y), "r"(vb[j].y));
                    *(uint2*)(Au + (wb + i) * APW + lane * 2) = p;   // STS.64
                }
            }
        }
        __syncwarp();   // STS visible to all lanes' LDS below

        // ---- GEMM: D[16x64] = A[16x128] x B[128x64], k16 steps ----
        float acc[8][4];
        #pragma unroll
        for (int nt = 0; nt < 8; nt++)
            #pragma unroll
            for (int c = 0; c < 4; c++) acc[nt][c] = 0.f;

        #pragma unroll
        for (int ks = 0; ks < 8; ks++) {
            const uint32_t* ar = Au + (wb + gid) * APW + 8 * ks + tig;
            const uint32_t a0 = ar[0];            // row gid,   k lo pair
            const uint32_t a2 = ar[4];            // row gid,   k hi pair
            const uint32_t a1 = ar[8 * APW];      // row gid+8, k lo pair
            const uint32_t a3 = ar[8 * APW + 4];  // row gid+8, k hi pair
            #pragma unroll
            for (int nt2 = 0; nt2 < 4; nt2++) {
                const uint4 bf = Bp[(ks * 4 + nt2) * 32 + lane];
                mma_f16(acc[2 * nt2],     a0, a1, a2, a3, bf.x, bf.y);
                mma_f16(acc[2 * nt2 + 1], a0, a1, a2, a3, bf.z, bf.w);
            }
        }
        __syncwarp();   // all lanes' A-LDS done before next unit's STS rewrite

        // ---- Epilogue: bias + ELU + dot(W2), 4-lane shfl reduce, sigmoid ----
        float p0 = 0.f, p1 = 0.f;
        #pragma unroll
        for (int nt = 0; nt < 8; nt++) {
            const int n = nt * 8 + 2 * tig;
            const float2 bb = *(const float2*)(b1s + n);   // LDS.64
            const float2 ww = *(const float2*)(w2s + n);   // LDS.64
            float x;
            x = acc[nt][0] + bb.x; p0 = fmaf(x > 0.f ? x : (__expf(x) - 1.f), ww.x, p0);
            x = acc[nt][1] + bb.y; p0 = fmaf(x > 0.f ? x : (__expf(x) - 1.f), ww.y, p0);
            x = acc[nt][2] + bb.x; p1 = fmaf(x > 0.f ? x : (__expf(x) - 1.f), ww.x, p1);
            x = acc[nt][3] + bb.y; p1 = fmaf(x > 0.f ? x : (__expf(x) - 1.f), ww.y, p1);
        }
        p0 += __shfl_xor_sync(0xffffffffu, p0, 1);
        p0 += __shfl_xor_sync(0xffffffffu, p0, 2);
        p1 += __shfl_xor_sync(0xffffffffu, p1, 1);
        p1 += __shfl_xor_sync(0xffffffffu, p1, 2);
        if (tig == 0) {
            out[e0 + gid]     = 1.0f / (1.0f + __expf(-(p0 + b2v)));
            out[e0 + gid + 8] = 1.0f / (1.0f + __expf(-(p1 + b2v)));
        }

        unit = nxt;
        myOff = nxtOff;
    }
}

extern "C" void kernel_launch(void* const* d_in, const int* in_sizes, int n_in,
                              void* d_out, int out_size) {
    const float* z_in   = (const float*)d_in[0];
    const float* z_out  = (const float*)d_in[1];
    const float* z_self = (const float*)d_in[2];
    const int*   eidx   = (const int*)d_in[3];
    const float* W1     = (const float*)d_in[4];
    const float* b1     = (const float*)d_in[5];
    const float* W2     = (const float*)d_in[6];
    const float* b2     = (const float*)d_in[7];
    float*       outp   = (float*)d_out;

    prep_kernel<<<NN * CC / 8 / 256, 256>>>(z_in, z_out, z_self);

    const int smem_bytes = SMEM_FLOATS * (int)sizeof(float);   // 51712
    cudaFuncSetAttribute(gemm_kernel,
                         cudaFuncAttributeMaxDynamicSharedMemorySize, smem_bytes);

    // PDL secondary launch: may begin while prep drains; device-side
    // griddepcontrol.wait gates table consumption.
    cudaLaunchConfig_t cfg = {};
    cfg.gridDim = dim3(MAIN_GRID, 1, 1);
    cfg.blockDim = dim3(MAIN_THREADS, 1, 1);
    cfg.dynamicSmemBytes = smem_bytes;
    cfg.stream = 0;
    cudaLaunchAttribute attrs[1];
    attrs[0].id = cudaLaunchAttributeProgrammaticStreamSerialization;
    attrs[0].val.programmaticStreamSerializationAllowed = 1;
    cfg.attrs = attrs;
    cfg.numAttrs = 1;
    cudaLaunchKernelEx(&cfg, gemm_kernel, eidx, W1, b1, W2, b2, outp);
}